// round 4
// baseline (speedup 1.0000x reference)
#include <cuda_runtime.h>
#include <math.h>

// ---------------- problem constants ----------------
#define MAXN   100000
#define MAXE   1600000
#define MAXG   128
#define FIN    12
#define NT     9                 // matmul terms: x, To1..4, Ti1..4
#define WCSZ   (NT * FIN * 64)   // 6912 combined weights (Z|H stacked on 64)

// ---------------- device scratch (static, no allocs) ----------------
__device__ float d_deg_out[MAXN];
__device__ float d_deg_in[MAXN];
__device__ float d_deg_out_inv[MAXN];
__device__ float d_deg_in_inv[MAXN];
__device__ float d_T[8][MAXN * FIN];   // 0..3: To1..To4, 4..7: Ti1..Ti4
__device__ float d_H[MAXN * 64];       // [N][64]: cols 0..31 = Z-preact, 32..63 = H~-preact
__device__ float d_Wc[WCSZ];           // [t][j][f2]
__device__ float d_gsum[MAXG * 4];
__device__ float d_gcnt[MAXG];

// ---------------- helpers ----------------
__device__ __forceinline__ void red_add4(float* p, float a, float b, float c, float d) {
    asm volatile("red.global.add.v4.f32 [%0], {%1, %2, %3, %4};"
                 :: "l"(__cvta_generic_to_global(p)), "f"(a), "f"(b), "f"(c), "f"(d)
                 : "memory");
}

// ---------------- kernels ----------------

// zero degrees/pool accumulators; seed Chebyshev buffers:
// T1o = 0, T1i = 0 (scatter targets), T2o = -x, T2i = -x (pre-init for 2*P(T1)-T0)
__global__ void init_all_kernel(const float* __restrict__ x, int Nn, int Gg) {
    int i = blockIdx.x * blockDim.x + threadIdx.x;
    int n12 = Nn * FIN;
    if (i < n12) {
        float xv = x[i];
        d_T[0][i] = 0.f;
        d_T[4][i] = 0.f;
        d_T[1][i] = -xv;
        d_T[5][i] = -xv;
    }
    if (i < Nn) { d_deg_out[i] = 0.f; d_deg_in[i] = 0.f; }
    if (i < Gg * 4) d_gsum[i] = 0.f;
    if (i < Gg)     d_gcnt[i] = 0.f;
}

__global__ void degrees_kernel(const int* __restrict__ row, const int* __restrict__ col,
                               const float* __restrict__ w, int E) {
    int e = blockIdx.x * blockDim.x + threadIdx.x;
    if (e >= E) return;
    float we = w[e];
    atomicAdd(&d_deg_out[row[e]], we);
    atomicAdd(&d_deg_in[col[e]], we);
}

__global__ void invdeg_kernel(int Nn) {
    int i = blockIdx.x * blockDim.x + threadIdx.x;
    if (i >= Nn) return;
    d_deg_out_inv[i] = 1.0f / d_deg_out[i];
    d_deg_in_inv[i]  = 1.0f / d_deg_in[i];
}

// Combined weights: Wc[t][j][f2]; f2<32 -> Z weights, f2>=32 -> H weights.
// t=0: W[0,0]+W[1,0] on x; t=1..4: W[0,k] (fwd chain); t=5..8: W[1,k] (rev chain).
__global__ void build_wc_kernel(const float* __restrict__ Wz, const float* __restrict__ Wh) {
    int idx = blockIdx.x * blockDim.x + threadIdx.x;
    if (idx >= WCSZ) return;
    int f2 = idx & 63;
    int j  = (idx >> 6) % FIN;
    int t  = idx / (FIN * 64);
    const float* W = (f2 < 32) ? Wz : Wh;
    int f = f2 & 31;
    float v;
    if (t == 0) {
        v = W[(0 * 5 + 0) * 1408 + j * 32 + f] + W[(1 * 5 + 0) * 1408 + j * 32 + f];
    } else if (t <= 4) {
        v = W[(0 * 5 + t) * 1408 + j * 32 + f];
    } else {
        v = W[(1 * 5 + (t - 4)) * 1408 + j * 32 + f];
    }
    d_Wc[idx] = v;
}

// Chebyshev pre-init: T[dA] = -T[sA], T[dB] = -T[sB]
__global__ void init_neg_kernel(int dA, int sA, int dB, int sB, int n12) {
    int i = blockIdx.x * blockDim.x + threadIdx.x;
    if (i >= n12) return;
    d_T[dA][i] = -d_T[sA][i];
    d_T[dB][i] = -d_T[sB][i];
}

// Fused fwd+rev diffusion scatter:
//   fwd: dst_o[col[e]] += factor * deg_out_inv[row[e]] * src_o[row[e]]
//   rev: dst_i[row[e]] += factor * deg_in_inv[row[e]]  * src_i[col[e]]
__global__ void prop_kernel(const int* __restrict__ row, const int* __restrict__ col,
                            const float* __restrict__ x,
                            int soid, int siid, int doid, int diid,
                            float factor, int E) {
    int e = blockIdx.x * blockDim.x + threadIdx.x;
    if (e >= E) return;
    const float* src_o = (soid < 0) ? x : d_T[soid];
    const float* src_i = (siid < 0) ? x : d_T[siid];
    float* dst_o = d_T[doid];
    float* dst_i = d_T[diid];

    int s = row[e], d = col[e];
    float a = d_deg_out_inv[s] * factor;
    float b = d_deg_in_inv[s] * factor;

    const float4* ho = (const float4*)(src_o + (size_t)s * FIN);
    const float4* hi = (const float4*)(src_i + (size_t)d * FIN);
    float4 o0 = ho[0], o1 = ho[1], o2 = ho[2];
    float4 i0 = hi[0], i1 = hi[1], i2 = hi[2];

    float* po = dst_o + (size_t)d * FIN;
    float* pi = dst_i + (size_t)s * FIN;
    red_add4(po + 0, a * o0.x, a * o0.y, a * o0.z, a * o0.w);
    red_add4(po + 4, a * o1.x, a * o1.y, a * o1.z, a * o1.w);
    red_add4(po + 8, a * o2.x, a * o2.y, a * o2.z, a * o2.w);
    red_add4(pi + 0, b * i0.x, b * i0.y, b * i0.z, b * i0.w);
    red_add4(pi + 4, b * i1.x, b * i1.y, b * i1.z, b * i1.w);
    red_add4(pi + 8, b * i2.x, b * i2.y, b * i2.z, b * i2.w);
}

// H[n][0..63] = sum_t sum_j S_t[n][j] * Wc[t][j][f2], packed-f32x2 FMA, Wc in shared.
__global__ __launch_bounds__(128) void matmul_kernel(const float* __restrict__ x, int Nn) {
    __shared__ float sWc[WCSZ];
    for (int i = threadIdx.x; i < WCSZ; i += blockDim.x) sWc[i] = d_Wc[i];
    __syncthreads();

    int n = blockIdx.x * blockDim.x + threadIdx.x;
    if (n >= Nn) return;

    unsigned long long acc[32];
#pragma unroll
    for (int p = 0; p < 32; p++) acc[p] = 0ULL;

#pragma unroll 1
    for (int t = 0; t < NT; t++) {
        const float* src = (t == 0) ? (x + (size_t)n * FIN) : (d_T[t - 1] + (size_t)n * FIN);
        float4 v0 = *(const float4*)(src);
        float4 v1 = *(const float4*)(src + 4);
        float4 v2 = *(const float4*)(src + 8);
        float vv[FIN] = {v0.x, v0.y, v0.z, v0.w, v1.x, v1.y, v1.z, v1.w,
                         v2.x, v2.y, v2.z, v2.w};
#pragma unroll
        for (int j = 0; j < FIN; j++) {
            unsigned long long tv2;
            asm("mov.b64 %0, {%1, %1};" : "=l"(tv2) : "r"(__float_as_uint(vv[j])));
            const unsigned long long* w2 =
                (const unsigned long long*)(sWc + (t * FIN + j) * 64);
#pragma unroll
            for (int p = 0; p < 32; p++) {
                unsigned long long wv = w2[p];
                asm("fma.rn.f32x2 %0, %1, %2, %0;" : "+l"(acc[p]) : "l"(tv2), "l"(wv));
            }
        }
    }

    unsigned long long* Hrow = (unsigned long long*)(d_H + (size_t)n * 64);
#pragma unroll
    for (int p = 0; p < 32; p++) Hrow[p] = acc[p];
}

// GRU gate (zero hidden state) + relu + 32x4 linear + mean-pool accumulate.
__global__ void gate_pool_kernel(const int* __restrict__ batch,
                                 const float* __restrict__ bz, const float* __restrict__ bh,
                                 const float* __restrict__ Wl, int Nn) {
    int n = blockIdx.x * blockDim.x + threadIdx.x;
    float y0 = 0.f, y1 = 0.f, y2 = 0.f, y3 = 0.f, cnt = 0.f;
    int g = -1;
    if (n < Nn) {
        g = batch[n];
        cnt = 1.f;
        const float* Hr = d_H + (size_t)n * 64;
#pragma unroll
        for (int f = 0; f < 32; f++) {
            float z  = 1.0f / (1.0f + expf(-(Hr[f] + bz[f])));
            float ht = tanhf(Hr[32 + f] + bh[f]);
            float v  = (1.0f - z) * ht;
            v = fmaxf(v, 0.0f);
            float4 w = *(const float4*)(Wl + f * 4);
            y0 += v * w.x; y1 += v * w.y; y2 += v * w.z; y3 += v * w.w;
        }
    }
    // warp-aggregated pooling (batch is sorted: most warps see one graph id)
    int g0 = __shfl_sync(0xffffffffu, g, 0);
    bool uni = __all_sync(0xffffffffu, g == g0);
    if (uni) {
        if (g0 >= 0) {
#pragma unroll
            for (int off = 16; off > 0; off >>= 1) {
                y0  += __shfl_down_sync(0xffffffffu, y0, off);
                y1  += __shfl_down_sync(0xffffffffu, y1, off);
                y2  += __shfl_down_sync(0xffffffffu, y2, off);
                y3  += __shfl_down_sync(0xffffffffu, y3, off);
                cnt += __shfl_down_sync(0xffffffffu, cnt, off);
            }
            if ((threadIdx.x & 31) == 0) {
                atomicAdd(&d_gsum[g0 * 4 + 0], y0);
                atomicAdd(&d_gsum[g0 * 4 + 1], y1);
                atomicAdd(&d_gsum[g0 * 4 + 2], y2);
                atomicAdd(&d_gsum[g0 * 4 + 3], y3);
                atomicAdd(&d_gcnt[g0], cnt);
            }
        }
    } else {
        if (g >= 0) {
            atomicAdd(&d_gsum[g * 4 + 0], y0);
            atomicAdd(&d_gsum[g * 4 + 1], y1);
            atomicAdd(&d_gsum[g * 4 + 2], y2);
            atomicAdd(&d_gsum[g * 4 + 3], y3);
            atomicAdd(&d_gcnt[g], cnt);
        }
    }
}

__global__ void finalize_kernel(float* __restrict__ out, const float* __restrict__ bl, int G4) {
    int idx = blockIdx.x * blockDim.x + threadIdx.x;
    if (idx >= G4) return;
    int g = idx >> 2, c = idx & 3;
    out[idx] = d_gsum[idx] / d_gcnt[g] + bl[c];
}

// ---------------- host launch ----------------
extern "C" void kernel_launch(void* const* d_in, const int* in_sizes, int n_in,
                              void* d_out, int out_size) {
    const float* x     = (const float*)d_in[0];
    const int*   ei    = (const int*)  d_in[1];
    const float* w     = (const float*)d_in[2];
    const int*   batch = (const int*)  d_in[3];
    const float* Wz    = (const float*)d_in[4];
    const float* bz    = (const float*)d_in[5];
    // d_in[6] = W_r, d_in[7] = b_r : unused (R gate multiplies the zero hidden state)
    const float* Wh    = (const float*)d_in[8];
    const float* bh    = (const float*)d_in[9];
    const float* Wl    = (const float*)d_in[10];
    const float* bl    = (const float*)d_in[11];
    float* out = (float*)d_out;

    int Nn = in_sizes[0] / FIN;        // 100000
    int E  = in_sizes[2];              // 1600000
    int Gg = out_size / 4;             // 100
    const int* row = ei;
    const int* col = ei + E;

    int n12 = Nn * FIN;
    dim3 blk(256);
    int gN12 = (n12 + 255) / 256;
    int gE   = (E + 255) / 256;
    int gNn  = (Nn + 255) / 256;

    init_all_kernel<<<gN12, blk>>>(x, Nn, Gg);
    degrees_kernel<<<gE, blk>>>(row, col, w, E);
    invdeg_kernel<<<gNn, blk>>>(Nn);
    build_wc_kernel<<<(WCSZ + 255) / 256, blk>>>(Wz, Wh);

    // Chebyshev diffusion: 4 fused (fwd+rev) propagation steps
    prop_kernel<<<gE, blk>>>(row, col, x, -1, -1, 0, 4, 1.0f, E);  // T1 = P(x)
    prop_kernel<<<gE, blk>>>(row, col, x,  0,  4, 1, 5, 2.0f, E);  // T2 = 2P(T1) - x (pre-seeded)
    init_neg_kernel<<<gN12, blk>>>(2, 0, 6, 4, n12);               // seed T3 = -T1
    prop_kernel<<<gE, blk>>>(row, col, x,  1,  5, 2, 6, 2.0f, E);  // T3 += 2P(T2)
    init_neg_kernel<<<gN12, blk>>>(3, 1, 7, 5, n12);               // seed T4 = -T2
    prop_kernel<<<gE, blk>>>(row, col, x,  2,  6, 3, 7, 2.0f, E);  // T4 += 2P(T3)

    matmul_kernel<<<(Nn + 127) / 128, 128>>>(x, Nn);
    gate_pool_kernel<<<gNn, blk>>>(batch, bz, bh, Wl, Nn);
    finalize_kernel<<<(Gg * 4 + 255) / 256, blk>>>(out, bl, Gg * 4);
}

// round 5
// speedup vs baseline: 1.9757x; 1.9757x over previous
#include <cuda_runtime.h>
#include <math.h>

// ---------------- problem constants ----------------
#define MAXN   100000
#define MAXE   1600000
#define MAXG   128
#define FIN    12
#define NT     9                 // matmul terms: x, To1..4, Ti1..4
#define WCSZ   (NT * FIN * 64)   // combined weights (Z|H stacked on 64)
#define PADE   (MAXE + 4 * MAXN) // padded edge-list bound
#define SCAN_B 512
#define NBMAX  ((MAXN + SCAN_B - 1) / SCAN_B)   // 196

// ---------------- device scratch (static, no allocs) ----------------
__device__ float d_deg_out[MAXN], d_deg_in[MAXN];
__device__ float d_doi[MAXN], d_dii[MAXN];
__device__ int   d_cnt_in[MAXN], d_cnt_out[MAXN];
__device__ int   d_off_in[MAXN], d_off_out[MAXN];
__device__ int   d_cur_in[MAXN], d_cur_out[MAXN];
__device__ int   d_bsumA[NBMAX], d_bsumB[NBMAX], d_boffA[NBMAX], d_boffB[NBMAX];
__device__ int   d_csc[PADE];    // grouped by dst: src indices  (fwd gather)
__device__ int   d_csr[PADE];    // grouped by src: dst indices  (rev gather)
__device__ float d_Xp[(MAXN + 1) * FIN];        // padded copy of x (+ zero row)
__device__ float d_S[5][(MAXN + 1) * FIN];      // scaled fwd chain S0..S4 (+ zero rows)
__device__ float d_Ti[4][(MAXN + 1) * FIN];     // rev chain Ti1..Ti4 (+ zero rows)
__device__ float d_H[MAXN * 64];                // [N][64]: 0..31 Z-preact, 32..63 H~-preact
__device__ float d_Wc[WCSZ];
__device__ float d_gsum[MAXG * 4];
__device__ float d_gcnt[MAXG];

// ---------------- kernels ----------------

__global__ void init_kernel(int Nn, int Gg) {
    int i = blockIdx.x * blockDim.x + threadIdx.x;
    if (i < Nn) {
        d_deg_out[i] = 0.f; d_deg_in[i] = 0.f;
        d_cnt_in[i] = 0;    d_cnt_out[i] = 0;
    }
    if (i < Gg * 4) d_gsum[i] = 0.f;
    if (i < Gg)     d_gcnt[i] = 0.f;
    if (i < FIN) {                 // zero sentinel rows (index MAXN)
        d_Xp[MAXN * FIN + i] = 0.f;
#pragma unroll
        for (int k = 0; k < 5; k++) d_S[k][MAXN * FIN + i] = 0.f;
#pragma unroll
        for (int k = 0; k < 4; k++) d_Ti[k][MAXN * FIN + i] = 0.f;
    }
}

// weighted degrees + unweighted count histograms, fused (one index load pass)
__global__ void degrees_hist_kernel(const int* __restrict__ row, const int* __restrict__ col,
                                    const float* __restrict__ w, int E) {
    int e = blockIdx.x * blockDim.x + threadIdx.x;
    if (e >= E) return;
    int s = row[e], d = col[e];
    float we = w[e];
    atomicAdd(&d_deg_out[s], we);
    atomicAdd(&d_deg_in[d], we);
    atomicAdd(&d_cnt_out[s], 1);
    atomicAdd(&d_cnt_in[d], 1);
}

// inverse degrees + padded x copy + S0 = doi .* x
__global__ void prep_kernel(const float* __restrict__ x, int Nn) {
    int n = blockIdx.x * blockDim.x + threadIdx.x;
    if (n >= Nn) return;
    float doi = 1.0f / d_deg_out[n];
    float dii = 1.0f / d_deg_in[n];
    d_doi[n] = doi; d_dii[n] = dii;
    const float4* xr = (const float4*)(x + (size_t)n * FIN);
    float4 v0 = xr[0], v1 = xr[1], v2 = xr[2];
    float4* xp = (float4*)(d_Xp + (size_t)n * FIN);
    xp[0] = v0; xp[1] = v1; xp[2] = v2;
    float4* s0 = (float4*)(d_S[0] + (size_t)n * FIN);
    s0[0] = make_float4(v0.x * doi, v0.y * doi, v0.z * doi, v0.w * doi);
    s0[1] = make_float4(v1.x * doi, v1.y * doi, v1.z * doi, v1.w * doi);
    s0[2] = make_float4(v2.x * doi, v2.y * doi, v2.z * doi, v2.w * doi);
}

// ---- 3-kernel exclusive scan of padded counts (both arrays at once) ----
__global__ void scanA_kernel(int Nn) {
    __shared__ int sA[SCAN_B], sB[SCAN_B];
    int t = threadIdx.x;
    int i = blockIdx.x * SCAN_B + t;
    int a = (i < Nn) ? ((d_cnt_in[i] + 3) & ~3) : 0;
    int b = (i < Nn) ? ((d_cnt_out[i] + 3) & ~3) : 0;
    sA[t] = a; sB[t] = b;
    __syncthreads();
    for (int off = 1; off < SCAN_B; off <<= 1) {
        int va = (t >= off) ? sA[t - off] : 0;
        int vb = (t >= off) ? sB[t - off] : 0;
        __syncthreads();
        sA[t] += va; sB[t] += vb;
        __syncthreads();
    }
    if (i < Nn) { d_off_in[i] = sA[t] - a; d_off_out[i] = sB[t] - b; }
    if (t == SCAN_B - 1) { d_bsumA[blockIdx.x] = sA[t]; d_bsumB[blockIdx.x] = sB[t]; }
}

__global__ void scanB_kernel(int nb) {
    __shared__ int sA[256], sB[256];
    int t = threadIdx.x;
    int a = (t < nb) ? d_bsumA[t] : 0;
    int b = (t < nb) ? d_bsumB[t] : 0;
    sA[t] = a; sB[t] = b;
    __syncthreads();
    for (int off = 1; off < 256; off <<= 1) {
        int va = (t >= off) ? sA[t - off] : 0;
        int vb = (t >= off) ? sB[t - off] : 0;
        __syncthreads();
        sA[t] += va; sB[t] += vb;
        __syncthreads();
    }
    if (t < nb) { d_boffA[t] = sA[t] - a; d_boffB[t] = sB[t] - b; }
}

__global__ void scanC_kernel(int Nn) {
    int i = blockIdx.x * blockDim.x + threadIdx.x;
    if (i >= Nn) return;
    int oi = d_off_in[i] + d_boffA[i / SCAN_B];
    int oo = d_off_out[i] + d_boffB[i / SCAN_B];
    d_off_in[i] = oi;  d_cur_in[i] = oi;    // cursors start at list base
    d_off_out[i] = oo; d_cur_out[i] = oo;
}

__global__ void fill_kernel(const int* __restrict__ row, const int* __restrict__ col, int E) {
    int e = blockIdx.x * blockDim.x + threadIdx.x;
    if (e >= E) return;
    int s = row[e], d = col[e];
    int p = atomicAdd(&d_cur_in[d], 1);
    d_csc[p] = s;
    int q = atomicAdd(&d_cur_out[s], 1);
    d_csr[q] = d;
}

// pad each list to a multiple of 4 with the zero-row sentinel index
__global__ void padfill_kernel(int Nn) {
    int n = blockIdx.x * blockDim.x + threadIdx.x;
    if (n >= Nn) return;
    {
        int c = d_cnt_in[n], b = d_off_in[n] + c, e = d_off_in[n] + ((c + 3) & ~3);
        for (int i = b; i < e; i++) d_csc[i] = MAXN;
    }
    {
        int c = d_cnt_out[n], b = d_off_out[n] + c, e = d_off_out[n] + ((c + 3) & ~3);
        for (int i = b; i < e; i++) d_csr[i] = MAXN;
    }
}

__global__ void build_wc_kernel(const float* __restrict__ Wz, const float* __restrict__ Wh) {
    int idx = blockIdx.x * blockDim.x + threadIdx.x;
    if (idx >= WCSZ) return;
    int f2 = idx & 63;
    int j  = (idx >> 6) % FIN;
    int t  = idx / (FIN * 64);
    const float* W = (f2 < 32) ? Wz : Wh;
    int f = f2 & 31;
    float v;
    if (t == 0)      v = W[0 * 1408 + j * 32 + f] + W[5 * 1408 + j * 32 + f];
    else if (t <= 4) v = W[(0 * 5 + t) * 1408 + j * 32 + f];
    else             v = W[(1 * 5 + (t - 4)) * 1408 + j * 32 + f];
    d_Wc[idx] = v;
}

// one gather side: out[n] = fac*diag[n]*sum_{edges(n)} src[idx] - prev[n]
__device__ __forceinline__ void gather_side(
    int n, const int* __restrict__ idxbuf,
    const int* __restrict__ off, const int* __restrict__ cnt,
    const float* __restrict__ diag,
    const float* __restrict__ src, const float* __restrict__ prev,
    float* __restrict__ dst, float fac)
{
    unsigned long long acc[6];
#pragma unroll
    for (int p = 0; p < 6; p++) acc[p] = 0ULL;

    int b = off[n];
    int e = b + ((cnt[n] + 3) & ~3);
    for (int i = b; i < e; i += 4) {
        int4 q = *(const int4*)(idxbuf + i);
        const ulonglong2* r0 = (const ulonglong2*)(src + (size_t)q.x * FIN);
        const ulonglong2* r1 = (const ulonglong2*)(src + (size_t)q.y * FIN);
        const ulonglong2* r2 = (const ulonglong2*)(src + (size_t)q.z * FIN);
        const ulonglong2* r3 = (const ulonglong2*)(src + (size_t)q.w * FIN);
        ulonglong2 a0 = r0[0], a1 = r0[1], a2 = r0[2];
        ulonglong2 b0 = r1[0], b1 = r1[1], b2 = r1[2];
        ulonglong2 c0 = r2[0], c1 = r2[1], c2 = r2[2];
        ulonglong2 d0 = r3[0], d1 = r3[1], d2 = r3[2];
#define ACC2(p, v) asm("add.rn.f32x2 %0, %0, %1;" : "+l"(acc[p]) : "l"(v))
        ACC2(0, a0.x); ACC2(1, a0.y); ACC2(2, a1.x); ACC2(3, a1.y); ACC2(4, a2.x); ACC2(5, a2.y);
        ACC2(0, b0.x); ACC2(1, b0.y); ACC2(2, b1.x); ACC2(3, b1.y); ACC2(4, b2.x); ACC2(5, b2.y);
        ACC2(0, c0.x); ACC2(1, c0.y); ACC2(2, c1.x); ACC2(3, c1.y); ACC2(4, c2.x); ACC2(5, c2.y);
        ACC2(0, d0.x); ACC2(1, d0.y); ACC2(2, d1.x); ACC2(3, d1.y); ACC2(4, d2.x); ACC2(5, d2.y);
#undef ACC2
    }

    float c = diag[n] * fac;
    float out[FIN];
#pragma unroll
    for (int p = 0; p < 6; p++) {
        float lo = __uint_as_float((unsigned)(acc[p] & 0xffffffffu));
        float hi = __uint_as_float((unsigned)(acc[p] >> 32));
        out[2 * p]     = c * lo;
        out[2 * p + 1] = c * hi;
    }
    if (prev) {
        const float4* pv = (const float4*)(prev + (size_t)n * FIN);
        float4 p0 = pv[0], p1 = pv[1], p2 = pv[2];
        out[0] -= p0.x; out[1] -= p0.y; out[2]  -= p0.z; out[3]  -= p0.w;
        out[4] -= p1.x; out[5] -= p1.y; out[6]  -= p1.z; out[7]  -= p1.w;
        out[8] -= p2.x; out[9] -= p2.y; out[10] -= p2.z; out[11] -= p2.w;
    }
    float4* dr = (float4*)(dst + (size_t)n * FIN);
    dr[0] = make_float4(out[0], out[1], out[2], out[3]);
    dr[1] = make_float4(out[4], out[5], out[6], out[7]);
    dr[2] = make_float4(out[8], out[9], out[10], out[11]);
}

// one Chebyshev step, both chains; threads [0,N) fwd, [N,2N) rev
__global__ __launch_bounds__(256) void gprop_kernel(
    const float* __restrict__ srcF, const float* __restrict__ prevF, float* __restrict__ dstF,
    const float* __restrict__ srcR, const float* __restrict__ prevR, float* __restrict__ dstR,
    float fac, int Nn)
{
    int tid = blockIdx.x * blockDim.x + threadIdx.x;
    if (tid < Nn) {
        gather_side(tid, d_csc, d_off_in, d_cnt_in, d_doi, srcF, prevF, dstF, fac);
    } else if (tid < 2 * Nn) {
        gather_side(tid - Nn, d_csr, d_off_out, d_cnt_out, d_dii, srcR, prevR, dstR, fac);
    }
}

// H[n][0..63] = x@Wc0 + sum_k (deg_out*S_k)@Wc_k + sum_k Ti_k@Wc_{4+k}
__global__ __launch_bounds__(128) void matmul_kernel(int Nn) {
    __shared__ float sWc[WCSZ];
    for (int i = threadIdx.x; i < WCSZ; i += blockDim.x) sWc[i] = d_Wc[i];
    __syncthreads();

    int n = blockIdx.x * blockDim.x + threadIdx.x;
    if (n >= Nn) return;
    float dout = d_deg_out[n];

    unsigned long long acc[32];
#pragma unroll
    for (int p = 0; p < 32; p++) acc[p] = 0ULL;

#pragma unroll 1
    for (int t = 0; t < NT; t++) {
        const float* src;
        float scale;
        if (t == 0)      { src = d_Xp + (size_t)n * FIN;         scale = 1.0f; }
        else if (t <= 4) { src = d_S[t] + (size_t)n * FIN;       scale = dout; }
        else             { src = d_Ti[t - 5] + (size_t)n * FIN;  scale = 1.0f; }
        float4 v0 = *(const float4*)(src);
        float4 v1 = *(const float4*)(src + 4);
        float4 v2 = *(const float4*)(src + 8);
        float vv[FIN] = {v0.x * scale, v0.y * scale, v0.z * scale, v0.w * scale,
                         v1.x * scale, v1.y * scale, v1.z * scale, v1.w * scale,
                         v2.x * scale, v2.y * scale, v2.z * scale, v2.w * scale};
#pragma unroll
        for (int j = 0; j < FIN; j++) {
            unsigned long long tv2;
            asm("mov.b64 %0, {%1, %1};" : "=l"(tv2) : "r"(__float_as_uint(vv[j])));
            const unsigned long long* w2 =
                (const unsigned long long*)(sWc + (t * FIN + j) * 64);
#pragma unroll
            for (int p = 0; p < 32; p++) {
                unsigned long long wv = w2[p];
                asm("fma.rn.f32x2 %0, %1, %2, %0;" : "+l"(acc[p]) : "l"(tv2), "l"(wv));
            }
        }
    }

    unsigned long long* Hrow = (unsigned long long*)(d_H + (size_t)n * 64);
#pragma unroll
    for (int p = 0; p < 32; p++) Hrow[p] = acc[p];
}

// GRU gate (zero hidden state) + relu + 32x4 linear + mean-pool accumulate
__global__ void gate_pool_kernel(const int* __restrict__ batch,
                                 const float* __restrict__ bz, const float* __restrict__ bh,
                                 const float* __restrict__ Wl, int Nn) {
    int n = blockIdx.x * blockDim.x + threadIdx.x;
    float y0 = 0.f, y1 = 0.f, y2 = 0.f, y3 = 0.f, cnt = 0.f;
    int g = -1;
    if (n < Nn) {
        g = batch[n];
        cnt = 1.f;
        const float* Hr = d_H + (size_t)n * 64;
#pragma unroll
        for (int f = 0; f < 32; f++) {
            float z  = 1.0f / (1.0f + expf(-(Hr[f] + bz[f])));
            float ht = tanhf(Hr[32 + f] + bh[f]);
            float v  = fmaxf((1.0f - z) * ht, 0.0f);
            float4 w = *(const float4*)(Wl + f * 4);
            y0 += v * w.x; y1 += v * w.y; y2 += v * w.z; y3 += v * w.w;
        }
    }
    int g0 = __shfl_sync(0xffffffffu, g, 0);
    bool uni = __all_sync(0xffffffffu, g == g0);
    if (uni) {
        if (g0 >= 0) {
#pragma unroll
            for (int off = 16; off > 0; off >>= 1) {
                y0  += __shfl_down_sync(0xffffffffu, y0, off);
                y1  += __shfl_down_sync(0xffffffffu, y1, off);
                y2  += __shfl_down_sync(0xffffffffu, y2, off);
                y3  += __shfl_down_sync(0xffffffffu, y3, off);
                cnt += __shfl_down_sync(0xffffffffu, cnt, off);
            }
            if ((threadIdx.x & 31) == 0) {
                atomicAdd(&d_gsum[g0 * 4 + 0], y0);
                atomicAdd(&d_gsum[g0 * 4 + 1], y1);
                atomicAdd(&d_gsum[g0 * 4 + 2], y2);
                atomicAdd(&d_gsum[g0 * 4 + 3], y3);
                atomicAdd(&d_gcnt[g0], cnt);
            }
        }
    } else if (g >= 0) {
        atomicAdd(&d_gsum[g * 4 + 0], y0);
        atomicAdd(&d_gsum[g * 4 + 1], y1);
        atomicAdd(&d_gsum[g * 4 + 2], y2);
        atomicAdd(&d_gsum[g * 4 + 3], y3);
        atomicAdd(&d_gcnt[g], cnt);
    }
}

__global__ void finalize_kernel(float* __restrict__ out, const float* __restrict__ bl, int G4) {
    int idx = blockIdx.x * blockDim.x + threadIdx.x;
    if (idx >= G4) return;
    int g = idx >> 2, c = idx & 3;
    out[idx] = d_gsum[idx] / d_gcnt[g] + bl[c];
}

// ---------------- host launch ----------------
extern "C" void kernel_launch(void* const* d_in, const int* in_sizes, int n_in,
                              void* d_out, int out_size) {
    const float* x     = (const float*)d_in[0];
    const int*   ei    = (const int*)  d_in[1];
    const float* w     = (const float*)d_in[2];
    const int*   batch = (const int*)  d_in[3];
    const float* Wz    = (const float*)d_in[4];
    const float* bz    = (const float*)d_in[5];
    // d_in[6]=W_r, d_in[7]=b_r unused (R gate multiplies the zero hidden state)
    const float* Wh    = (const float*)d_in[8];
    const float* bh    = (const float*)d_in[9];
    const float* Wl    = (const float*)d_in[10];
    const float* bl    = (const float*)d_in[11];
    float* out = (float*)d_out;

    int Nn = in_sizes[0] / FIN;        // 100000
    int E  = in_sizes[2];              // 1600000
    int Gg = out_size / 4;             // 100
    const int* row = ei;
    const int* col = ei + E;

    dim3 blk(256);
    int gE  = (E + 255) / 256;
    int gNn = (Nn + 255) / 256;
    int g2N = (2 * Nn + 255) / 256;
    int nb  = (Nn + SCAN_B - 1) / SCAN_B;

    static float *Xpp = nullptr, *Sp = nullptr, *Tp = nullptr;
    if (!Xpp) {
        cudaGetSymbolAddress((void**)&Xpp, d_Xp);
        cudaGetSymbolAddress((void**)&Sp, d_S);
        cudaGetSymbolAddress((void**)&Tp, d_Ti);
    }
    const size_t RSZ = (size_t)(MAXN + 1) * FIN;
    float* S0p = Sp;            float* S1p = Sp + RSZ;      float* S2p = Sp + 2 * RSZ;
    float* S3p = Sp + 3 * RSZ;  float* S4p = Sp + 4 * RSZ;
    float* T1p = Tp;            float* T2p = Tp + RSZ;
    float* T3p = Tp + 2 * RSZ;  float* T4p = Tp + 3 * RSZ;

    init_kernel<<<gNn, blk>>>(Nn, Gg);
    degrees_hist_kernel<<<gE, blk>>>(row, col, w, E);
    prep_kernel<<<gNn, blk>>>(x, Nn);
    scanA_kernel<<<nb, SCAN_B>>>(Nn);
    scanB_kernel<<<1, 256>>>(nb);
    scanC_kernel<<<gNn, blk>>>(Nn);
    fill_kernel<<<gE, blk>>>(row, col, E);
    padfill_kernel<<<gNn, blk>>>(Nn);
    build_wc_kernel<<<(WCSZ + 255) / 256, blk>>>(Wz, Wh);

    // Chebyshev steps (fwd chain in scaled S-space, rev chain direct)
    gprop_kernel<<<g2N, blk>>>(S0p, nullptr, S1p, Xpp, nullptr, T1p, 1.0f, Nn);
    gprop_kernel<<<g2N, blk>>>(S1p, S0p,     S2p, T1p, Xpp,     T2p, 2.0f, Nn);
    gprop_kernel<<<g2N, blk>>>(S2p, S1p,     S3p, T2p, T1p,     T3p, 2.0f, Nn);
    gprop_kernel<<<g2N, blk>>>(S3p, S2p,     S4p, T3p, T2p,     T4p, 2.0f, Nn);

    matmul_kernel<<<(Nn + 127) / 128, 128>>>(Nn);
    gate_pool_kernel<<<gNn, blk>>>(batch, bz, bh, Wl, Nn);
    finalize_kernel<<<(Gg * 4 + 255) / 256, blk>>>(out, bl, Gg * 4);
}